// round 15
// baseline (speedup 1.0000x reference)
#include <cuda_runtime.h>
#include <math.h>

#define BB    32
#define NIN   2312
#define NHID  512
#define NOUT  10
#define TT    350
#define WPT   73              // ceil(NIN/32)
#define NCOL  (BB * TT)       // 11200

#define HALF0 1160            // rows [0,1160) -> half 0, [1160,2312) -> half 1
#define HROWS 1164            // per-half rows incl. zero-pad slots
#define IDXC2 192             // per-half index capacity (prefetch depth 4 safe)
#define CAPU  144

#define THETA  10.0f
#define D_REF  0.36787944117144233f    // exp(-1)
#define C_REF  -54.365636569180905f    // -2*10*e

#define ADDX2(d, a, b) asm("add.rn.f32x2 %0, %1, %2;" : "=l"(d) : "l"(a), "l"(b))

// ---- compile-time SRM kernel: eps(j) = (j/10)*exp(1-j/10), evaluated by cc front-end
__host__ __device__ constexpr double cexp_pos(double x) {
    double s = 1.0, term = 1.0;
    for (int i = 1; i < 60; i++) { term *= x / i; s += term; }
    return s;
}
__host__ __device__ constexpr float epsf(int j) {
    if (j < 1 || j > 99) return 0.f;
    double x = 1.0 - j / 10.0;
    double e = (x >= 0.0) ? cexp_pos(x) : 1.0 / cexp_pos(-x);
    return (float)((j / 10.0) * e);
}

// Guaranteed-folded FIR step: constexpr coefficient -> FFMA with immediate.
template<int J, int R> struct AccR {
    static __device__ __forceinline__ void run(float x, float acc[8]) {
        if constexpr (R < 8) {
            if constexpr (R - J >= 1 && R - J <= 99) {
                constexpr float c = epsf(R - J);      // compile-time by construction
                acc[R] = fmaf(c, x, acc[R]);
            }
            AccR<J, R + 1>::run(x, acc);
        }
    }
};
template<int J> struct JStep {
    static __device__ __forceinline__ void run(const float* base, float acc[8]) {
        if constexpr (J >= -99) {
            float x = base[J * 32];
            AccR<J, 0>::run(x, acc);
            JStep<J - 1>::run(base, acc);
        }
    }
};

// ---------------- scratch (device globals; no cudaMalloc allowed) ----------------
__device__ float          g_W1Tc[16 * 2 * HROWS * 32];   // [hc][half][local][32]  4.77 MB
__device__ unsigned       g_PK  [NCOL * WPT];            // packed spike bits      3.3 MB
__device__ unsigned short g_IDXA[NCOL * IDXC2 + 32];     // half-0 local indices
__device__ unsigned short g_IDXB[NCOL * IDXC2 + 32];     // half-1 local indices
__device__ int            g_CNTA[NCOL];
__device__ int            g_CNTB[NCOL];
__device__ float          g_Y1a [NCOL * NHID];           // partial sums, half 0
__device__ float          g_Y1b [NCOL * NHID];           // partial sums, half 1
__device__ float          g_S1  [NCOL * NHID];           // hidden spikes
__device__ float          g_U2  [NCOL * NOUT];

// ------ W1 [h][i] -> [hc=h/32][half][local][hl=h%32]; pad rows zeroed in-line -----
__global__ void k_prep(const float* __restrict__ W1) {
    __shared__ float s[32][33];
    int i = blockIdx.x * 32 + threadIdx.x;
    int h = blockIdx.y * 32 + threadIdx.y;
    s[threadIdx.y][threadIdx.x] = (i < NIN && h < NHID) ? W1[h * NIN + i] : 0.f;
    __syncthreads();
    int i2 = blockIdx.x * 32 + threadIdx.y;
    int h2 = blockIdx.y * 32 + threadIdx.x;
    int hc = h2 >> 5, hl = h2 & 31;
    if (i2 < NIN) {
        int half = (i2 >= HALF0);
        int local = i2 - half * HALF0;
        g_W1Tc[((size_t)(hc * 2 + half) * HROWS + local) * 32 + hl] = s[threadIdx.x][threadIdx.y];
    } else {
        int off = i2 - NIN;                         // 0..23 (block x = 72 only)
        int half, local;
        if (off < 4)       { half = 0; local = 1160 + off; }
        else if (off < 16) { half = 1; local = 1152 + (off - 4); }
        else return;
        g_W1Tc[((size_t)(hc * 2 + half) * HROWS + local) * 32 + hl] = 0.f;
    }
}

// ---------------- pack input spikes: [b][i][t] -> bits [b][t][i/32] ----------------
__global__ void k_pack(const float* __restrict__ A) {
    __shared__ unsigned char s[32][33];
    int b  = blockIdx.x;
    int i0 = blockIdx.y * 32;
    int t0 = blockIdx.z * 32;
    int i = i0 + threadIdx.y;
    int t = t0 + threadIdx.x;
    unsigned char bit = 0;
    if (i < NIN && t < TT) bit = (A[((size_t)b * NIN + i) * TT + t] > 0.5f) ? 1 : 0;
    s[threadIdx.y][threadIdx.x] = bit;
    __syncthreads();
    if (threadIdx.y == 0) {
        int t2 = t0 + threadIdx.x;
        if (t2 < TT) {
            unsigned w = 0;
#pragma unroll
            for (int y = 0; y < 32; y++) w |= ((unsigned)s[y][threadIdx.x]) << y;
            g_PK[(b * TT + t2) * WPT + blockIdx.y] = w;
        }
    }
}

// ---------------- per-(b,t) local index lists for both halves --------------------
__global__ void k_extract() {
    __shared__ unsigned wsh[WPT];
    __shared__ int cA[WPT], cB[WPT], oA[WPT], oB[WPT];
    __shared__ int totA, totB;
    int bt = blockIdx.x, tid = threadIdx.x;
    if (tid < WPT) {
        unsigned w = g_PK[bt * WPT + tid];
        wsh[tid] = w;
        unsigned maskA = (tid < 36) ? 0xFFFFFFFFu : (tid == 36 ? 0xFFu : 0u);
        cA[tid] = __popc(w & maskA);
        cB[tid] = __popc(w & ~maskA);
    }
    __syncthreads();
    if (tid == 0) { int r = 0; for (int j = 0; j < WPT; j++) { oA[j] = r; r += cA[j]; } totA = r; }
    if (tid == 32){ int r = 0; for (int j = 0; j < WPT; j++) { oB[j] = r; r += cB[j]; } totB = r; }
    __syncthreads();
    if (tid < WPT) {
        unsigned w = wsh[tid];
        int a = oA[tid], b = oB[tid];
        while (w) {
            int bp = __ffs(w) - 1; w &= w - 1;
            int gi = tid * 32 + bp;
            if (gi < HALF0) { if (a < CAPU) g_IDXA[(size_t)bt * IDXC2 + a] = (unsigned short)gi; a++; }
            else            { if (b < CAPU) g_IDXB[(size_t)bt * IDXC2 + b] = (unsigned short)(gi - HALF0); b++; }
        }
    }
    __syncthreads();
    int tA = min(totA, CAPU), pA = min((tA + 7) & ~7, CAPU);
    int tB = min(totB, CAPU), pB = min((tB + 7) & ~7, CAPU);
    if (tid == 0) { g_CNTA[bt] = pA; g_CNTB[bt] = pB; }
    // pad to count boundary AND fill the +4-group prefetch window with zero rows
    for (int j = tA + tid; j < pA + 32 && j < IDXC2; j += blockDim.x)
        g_IDXA[(size_t)bt * IDXC2 + j] = (unsigned short)1160;   // half-0 zero row
    for (int j = tB + tid; j < pB + 32 && j < IDXC2; j += blockDim.x)
        g_IDXB[(size_t)bt * IDXC2 + j] = (unsigned short)1152;   // half-1 zero row
}

// ------- SpMM: conflict-free quarter-warp rows, depth-4 index prefetch -----------
#define SPMM_SMEM (HROWS * 128)
#define COLCHUNK 1280
__global__ void __launch_bounds__(1024, 1) k_spmm() {
    extern __shared__ char smraw[];
    const ulonglong2* sW = (const ulonglong2*)smraw;   // HROWS rows x 128 B
    int tid  = threadIdx.x;
    int hc   = blockIdx.y >> 1;
    int half = blockIdx.y & 1;

    const float4* wsrc = (const float4*)(g_W1Tc + (size_t)(hc * 2 + half) * HROWS * 32);
    float4* sWf = (float4*)smraw;
    for (int i = tid; i < HROWS * 8; i += 1024) sWf[i] = wsrc[i];
    __syncthreads();

    const unsigned short* IDX = half ? g_IDXB : g_IDXA;
    const int*            CNT = half ? g_CNTB : g_CNTA;
    float*                Y   = half ? g_Y1b  : g_Y1a;

    int h4    = tid & 7;
    int cbase = blockIdx.x * COLCHUNK + (tid >> 3);    // 128 columns in flight
#pragma unroll 1
    for (int p = 0; p < COLCHUNK / 128; p++) {
        int col = cbase + p * 128;
        if (col >= NCOL) break;
        int ng = CNT[col] >> 3;
        const uint4* il = (const uint4*)(IDX + (size_t)col * IDXC2);
        unsigned long long a0x = 0, a0y = 0, a1x = 0, a1y = 0;
        if (ng) {
            uint4 pk0 = __ldg(il);                     // depth-4 prefetch ring
            uint4 pk1 = __ldg(il + 1);
            uint4 pk2 = __ldg(il + 2);
            uint4 pk3 = __ldg(il + 3);
#pragma unroll 4
            for (int g = 0; g < ng; g++) {
                uint4 nx = __ldg(il + g + 4);          // lists padded: safe
                int i0 = pk0.x & 0xffff, i1 = pk0.x >> 16;
                int i2 = pk0.y & 0xffff, i3 = pk0.y >> 16;
                {   // first half of group: 4 weight rows resident
                    ulonglong2 w0 = sW[i0 * 8 + h4];
                    ulonglong2 w1 = sW[i1 * 8 + h4];
                    ulonglong2 w2 = sW[i2 * 8 + h4];
                    ulonglong2 w3 = sW[i3 * 8 + h4];
                    ADDX2(a0x, a0x, w0.x); ADDX2(a0y, a0y, w0.y);
                    ADDX2(a1x, a1x, w1.x); ADDX2(a1y, a1y, w1.y);
                    ADDX2(a0x, a0x, w2.x); ADDX2(a0y, a0y, w2.y);
                    ADDX2(a1x, a1x, w3.x); ADDX2(a1y, a1y, w3.y);
                }
                int i4 = pk0.z & 0xffff, i5 = pk0.z >> 16;
                int i6 = pk0.w & 0xffff, i7 = pk0.w >> 16;
                {   // second half: temps reused -> registers freed for the ring
                    ulonglong2 w4 = sW[i4 * 8 + h4];
                    ulonglong2 w5 = sW[i5 * 8 + h4];
                    ulonglong2 w6 = sW[i6 * 8 + h4];
                    ulonglong2 w7 = sW[i7 * 8 + h4];
                    ADDX2(a0x, a0x, w4.x); ADDX2(a0y, a0y, w4.y);
                    ADDX2(a1x, a1x, w5.x); ADDX2(a1y, a1y, w5.y);
                    ADDX2(a0x, a0x, w6.x); ADDX2(a0y, a0y, w6.y);
                    ADDX2(a1x, a1x, w7.x); ADDX2(a1y, a1y, w7.y);
                }
                pk0 = pk1; pk1 = pk2; pk2 = pk3; pk3 = nx;   // renamed by unroll
            }
        }
        float2 p0 = *(float2*)&a0x, q0 = *(float2*)&a0y;
        float2 p1 = *(float2*)&a1x, q1 = *(float2*)&a1y;
        float4 r;
        r.x = p0.x + p1.x; r.y = p0.y + p1.y;
        r.z = q0.x + q1.x; r.w = q0.y + q1.y;
        ((float4*)Y)[(size_t)col * 128 + hc * 8 + h4] = r;
    }
}

// ---- FIR1: template-folded eps immediates (FFMA-imm), fused spike IIR -----------
#define FPAD  112
#define TROWS (FPAD + 384)    // 496
#define FIR_SMEM ((TROWS * 32 + TT * 32) * 4)
__global__ void __launch_bounds__(256, 2) k_fir_spike1() {
    extern __shared__ float sm[];
    float* tile = sm;                     // [TROWS][32], zero-padded front/back
    float* usm  = sm + TROWS * 32;        // [350][32]
    int tid = threadIdx.x;
    int b   = blockIdx.x >> 4;
    int h0  = (blockIdx.x & 15) * 32;

    for (int i = tid; i < FPAD * 32; i += 256) tile[i] = 0.f;
    for (int i = tid; i < (TROWS - FPAD - TT) * 32; i += 256) tile[(FPAD + TT) * 32 + i] = 0.f;
    for (int i = tid; i < TT * 32; i += 256) {
        int t = i >> 5, hl = i & 31;
        size_t off = ((size_t)(b * TT + t)) * NHID + h0 + hl;
        tile[(FPAD + t) * 32 + hl] = g_Y1a[off] + g_Y1b[off];
    }
    __syncthreads();

    int hl = tid & 31, rg = tid >> 5;
#pragma unroll 1
    for (int m = 0; m < 6; m++) {
        int t0 = m * 64 + rg * 8;         // 8 outputs per thread; rg uniform per warp
        if (t0 >= TT) break;
        float acc[8] = {0, 0, 0, 0, 0, 0, 0, 0};
        const float* base = tile + (FPAD + t0) * 32 + hl;
        JStep<6>::run(base, acc);         // j = 6 .. -99, validated order
#pragma unroll
        for (int r = 0; r < 8; r++) {
            int t = t0 + r;
            if (t < TT) usm[t * 32 + hl] = acc[r];
        }
    }
    __syncthreads();

    if (tid < 32) {                        // per-h refractory IIR over t
        float a = 0.f, rb = 0.f;
        size_t obase = ((size_t)b * TT) * NHID + h0 + tid;
        for (int t = 0; t < TT; t++) {
            float u  = usm[t * 32 + tid] + C_REF * rb;
            float s  = (u >= THETA) ? 1.f : 0.f;
            float an = D_REF * a + s;
            rb = D_REF * rb + D_REF * a;
            a  = an;
            g_S1[obase + (size_t)t * NHID] = s;
        }
    }
}

// ---------------- GEMV2 + FIR2: t-chunked, overlap recompute --------------------
#define TCHUNK 70
#define GEMV_SMEM ((64 * NHID + 169 * NOUT + 128) * 4)
__global__ void __launch_bounds__(512, 1) k_gemv2(const float* __restrict__ W2) {
    extern __shared__ float sm[];
    float* sS1  = sm;                        // [64][512]
    float* sY2  = sm + 64 * NHID;            // [169][10], slot s = row (tc-99)+s
    float* seps = sm + 64 * NHID + 169 * NOUT;
    int tid = threadIdx.x;
    int b   = blockIdx.x;
    int tc  = blockIdx.y * TCHUNK;
    int base = tc - 99;
    int rlo = max(0, base), rhi = tc + TCHUNK;

    if (tid < 128) seps[tid] = (tid >= 1 && tid < 100)
                               ? (float)((tid / 10.0) * exp(1.0 - tid / 10.0)) : 0.f;
    for (int i = tid; i < 169 * NOUT; i += 512) sY2[i] = 0.f;

    int wid = tid >> 5, lane = tid & 31;
    for (int r0 = rlo; r0 < rhi; r0 += 64) {
        int rows = min(64, rhi - r0);
        __syncthreads();
        const float4* src = (const float4*)(g_S1 + ((size_t)(b * TT + r0)) * NHID);
        for (int i = tid; i < rows * 128; i += 512) ((float4*)sS1)[i] = src[i];
        __syncthreads();
        for (int task = wid; task < rows * NOUT; task += 16) {
            int tl = task / NOUT, o = task - tl * NOUT;
            float acc = 0.f;
            const float* sp = sS1 + tl * NHID;
            const float* wp = W2 + o * NHID;
#pragma unroll 4
            for (int h = lane; h < NHID; h += 32) acc = fmaf(sp[h], wp[h], acc);
#pragma unroll
            for (int ofs = 16; ofs; ofs >>= 1) acc += __shfl_down_sync(0xffffffffu, acc, ofs);
            if (lane == 0) sY2[(r0 + tl - base) * NOUT + o] = acc;
        }
    }
    __syncthreads();
    for (int i = tid; i < TCHUNK * NOUT; i += 512) {
        int tl = i / NOUT, o = i - tl * NOUT;
        int t = tc + tl;
        float acc = 0.f;
#pragma unroll 4
        for (int k = 1; k < 100; k++)
            acc = fmaf(seps[k], sY2[(t - k - base) * NOUT + o], acc);
        g_U2[(b * TT + t) * NOUT + o] = acc;
    }
}

// ---------------- spike2 IIR (smem-staged, per-batch block) ----------------------
__global__ void __launch_bounds__(256, 4) k_spike2(float* __restrict__ out) {
    __shared__ float su[TT * NOUT];
    __shared__ float ss[NOUT * TT];
    int b = blockIdx.x, tid = threadIdx.x;
    const float4* src = (const float4*)(g_U2 + (size_t)b * TT * NOUT);
    for (int i = tid; i < TT * NOUT / 2; i += 256) {
        float4 v = src[i];
        su[i * 4] = v.x; su[i * 4 + 1] = v.y; su[i * 4 + 2] = v.z; su[i * 4 + 3] = v.w;
    }
    __syncthreads();
    if (tid < NOUT) {
        float a = 0.f, rb = 0.f;
        for (int t = 0; t < TT; t++) {
            float u  = su[t * NOUT + tid] + C_REF * rb;
            float s  = (u >= THETA) ? 1.f : 0.f;
            float an = D_REF * a + s;
            rb = D_REF * rb + D_REF * a;
            a  = an;
            ss[tid * TT + t] = s;
        }
    }
    __syncthreads();
    for (int i = tid; i < NOUT * TT; i += 256)
        out[(size_t)b * NOUT * TT + i] = ss[i];
}

extern "C" void kernel_launch(void* const* d_in, const int* in_sizes, int n_in,
                              void* d_out, int out_size) {
    const float* A  = nullptr;   // spikeInput [B][NIN][T]
    const float* W1 = nullptr;   // [NHID][NIN]
    const float* W2 = nullptr;   // [NOUT][NHID]
    for (int i = 0; i < n_in; i++) {
        if      (in_sizes[i] == BB * NIN * TT) A  = (const float*)d_in[i];
        else if (in_sizes[i] == NHID * NIN)    W1 = (const float*)d_in[i];
        else if (in_sizes[i] == NOUT * NHID)   W2 = (const float*)d_in[i];
    }
    float* out = (float*)d_out;

    cudaFuncSetAttribute(k_spmm,       cudaFuncAttributeMaxDynamicSharedMemorySize, SPMM_SMEM);
    cudaFuncSetAttribute(k_fir_spike1, cudaFuncAttributeMaxDynamicSharedMemorySize, FIR_SMEM);
    cudaFuncSetAttribute(k_gemv2,      cudaFuncAttributeMaxDynamicSharedMemorySize, GEMV_SMEM);

    k_prep   <<<dim3(73, 16), dim3(32, 32)>>>(W1);          // pads zeroed in-line
    k_pack   <<<dim3(BB, WPT, 11), dim3(32, 32)>>>(A);
    k_extract<<<NCOL, 128>>>();
    k_spmm   <<<dim3(9, 32), 1024, SPMM_SMEM>>>();          // launch #4 -> ncu window
    k_fir_spike1<<<512, 256, FIR_SMEM>>>();
    k_gemv2  <<<dim3(BB, TT / TCHUNK), 512, GEMV_SMEM>>>(W2);
    k_spike2 <<<BB, 256>>>(out);
}

// round 16
// speedup vs baseline: 1.0609x; 1.0609x over previous
#include <cuda_runtime.h>
#include <math.h>

#define BB    32
#define NIN   2312
#define NHID  512
#define NOUT  10
#define TT    350
#define WPT   73              // ceil(NIN/32)
#define NCOL  (BB * TT)       // 11200

#define HALF0 1160            // rows [0,1160) -> half 0, [1160,2312) -> half 1
#define HROWS 1164            // per-half rows incl. zero-pad slots
#define IDXC2 160             // per-half index capacity
#define CAPU  144

#define THETA  10.0f
#define D_REF  0.36787944117144233f    // exp(-1)
#define C_REF  -54.365636569180905f    // -2*10*e

#define ADDX2(d, a, b) asm("add.rn.f32x2 %0, %1, %2;" : "=l"(d) : "l"(a), "l"(b))

// ---- compile-time SRM kernel: eps(j) = (j/10)*exp(1-j/10) ----
__host__ __device__ constexpr double cexp_pos(double x) {
    double s = 1.0, term = 1.0;
    for (int i = 1; i < 60; i++) { term *= x / i; s += term; }
    return s;
}
__host__ __device__ constexpr float epsf(int j) {
    if (j < 1 || j > 99) return 0.f;
    double x = 1.0 - j / 10.0;
    double e = (x >= 0.0) ? cexp_pos(x) : 1.0 / cexp_pos(-x);
    return (float)((j / 10.0) * e);
}

// Guaranteed-folded FIR step: constexpr coefficient -> FFMA with immediate.
template<int J, int R> struct AccR {
    static __device__ __forceinline__ void run(float x, float acc[8]) {
        if constexpr (R < 8) {
            if constexpr (R - J >= 1 && R - J <= 99) {
                constexpr float c = epsf(R - J);
                acc[R] = fmaf(c, x, acc[R]);
            }
            AccR<J, R + 1>::run(x, acc);
        }
    }
};
template<int J> struct JStep {
    static __device__ __forceinline__ void run(const float* base, float acc[8]) {
        if constexpr (J >= -99) {
            float x = base[J * 32];
            AccR<J, 0>::run(x, acc);
            JStep<J - 1>::run(base, acc);
        }
    }
};

// ---------------- scratch (device globals; no cudaMalloc allowed) ----------------
__device__ float          g_W1Tc[16 * 2 * HROWS * 32];   // [hc][half][local][32]  4.77 MB
__device__ unsigned short g_IDXA[NCOL * IDXC2 + 16];     // half-0 local indices
__device__ unsigned short g_IDXB[NCOL * IDXC2 + 16];     // half-1 local indices
__device__ int            g_CNTA[NCOL];
__device__ int            g_CNTB[NCOL];
__device__ float          g_Y1a [NCOL * NHID];           // partial sums, half 0
__device__ float          g_Y1b [NCOL * NHID];           // partial sums, half 1
__device__ float          g_S1  [NCOL * NHID];           // hidden spikes
__device__ float          g_U2  [NCOL * NOUT];

// ------ W1 [h][i] -> [hc=h/32][half][local][hl=h%32]; pad rows zeroed in-line -----
__global__ void k_prep(const float* __restrict__ W1) {
    __shared__ float s[32][33];
    int i = blockIdx.x * 32 + threadIdx.x;
    int h = blockIdx.y * 32 + threadIdx.y;
    s[threadIdx.y][threadIdx.x] = (i < NIN && h < NHID) ? W1[h * NIN + i] : 0.f;
    __syncthreads();
    int i2 = blockIdx.x * 32 + threadIdx.y;
    int h2 = blockIdx.y * 32 + threadIdx.x;
    int hc = h2 >> 5, hl = h2 & 31;
    if (i2 < NIN) {
        int half = (i2 >= HALF0);
        int local = i2 - half * HALF0;
        g_W1Tc[((size_t)(hc * 2 + half) * HROWS + local) * 32 + hl] = s[threadIdx.x][threadIdx.y];
    } else {
        int off = i2 - NIN;                         // 0..23 (block x = 72 only)
        int half, local;
        if (off < 4)       { half = 0; local = 1160 + off; }
        else if (off < 16) { half = 1; local = 1152 + (off - 4); }
        else return;
        g_W1Tc[((size_t)(hc * 2 + half) * HROWS + local) * 32 + hl] = 0.f;
    }
}

// ---- fused pack+extract: ballot word-build + warp-per-column index extraction ---
// Output (lists, counts, padding) byte-identical to the old k_pack + k_extract.
__global__ void __launch_bounds__(1024) k_packex(const float* __restrict__ A) {
    __shared__ unsigned char sbit[32][33];
    __shared__ unsigned wsh[WPT][33];
    int tid  = threadIdx.x;
    int lane = tid & 31, wq = tid >> 5;
    int b  = blockIdx.x;
    int tc = blockIdx.y;                           // 0..10

    // phase 1: build bit words. warp wq loads row i (coalesced along t),
    // then reads the smem transpose and ballots one 32-bit word per column.
    for (int ic = 0; ic < WPT; ic++) {
        int i = ic * 32 + wq;
        int t = tc * 32 + lane;
        unsigned char bit = 0;
        if (i < NIN && t < TT) bit = (A[((size_t)b * NIN + i) * TT + t] > 0.5f) ? 1 : 0;
        __syncthreads();                           // prev iter's reads done
        sbit[wq][lane] = bit;
        __syncthreads();
        unsigned char mybit = sbit[lane][wq];      // column wq, i-bit = lane
        unsigned word = __ballot_sync(0xffffffffu, mybit);
        if (lane == 0) wsh[ic][wq] = word;
    }
    __syncthreads();

    // phase 2: warp wq owns column t = tc*32+wq. Lanes own contiguous word ranges.
    int t = tc * 32 + wq;
    if (t >= TT) return;                           // warp-uniform; no syncs below
    int col = b * TT + t;
    int w0 = (lane < 9) ? 3 * lane : 27 + 2 * (lane - 9);
    int nw = (lane < 9) ? 3 : 2;
    unsigned myw[3] = {0, 0, 0};
    unsigned cA = 0, cB = 0;
    for (int k = 0; k < nw; k++) {
        unsigned w = wsh[w0 + k][wq];
        myw[k] = w;
        int widx = w0 + k;
        if (widx < 36)       cA += __popc(w);
        else if (widx == 36) { cA += __popc(w & 0xFFu); cB += __popc(w >> 8); }
        else                 cB += __popc(w);
    }
    unsigned ia = cA, ib = cB;                     // inclusive scan
#pragma unroll
    for (int d = 1; d < 32; d <<= 1) {
        unsigned ta = __shfl_up_sync(0xffffffffu, ia, d);
        unsigned tb = __shfl_up_sync(0xffffffffu, ib, d);
        if (lane >= d) { ia += ta; ib += tb; }
    }
    unsigned offA = ia - cA, offB = ib - cB;       // exclusive
    unsigned totA = __shfl_sync(0xffffffffu, ia, 31);
    unsigned totB = __shfl_sync(0xffffffffu, ib, 31);
    unsigned short* dstA = g_IDXA + (size_t)col * IDXC2;
    unsigned short* dstB = g_IDXB + (size_t)col * IDXC2;
    for (int k = 0; k < nw; k++) {
        unsigned w = myw[k];
        int base = (w0 + k) * 32;
        while (w) {
            int bp = __ffs(w) - 1; w &= w - 1;
            int gi = base + bp;
            if (gi < HALF0) { if (offA < CAPU) dstA[offA] = (unsigned short)gi; offA++; }
            else            { if (offB < CAPU) dstB[offB] = (unsigned short)(gi - HALF0); offB++; }
        }
    }
    int tA = min((int)totA, CAPU), pA = min((tA + 7) & ~7, CAPU);
    int tB = min((int)totB, CAPU), pB = min((tB + 7) & ~7, CAPU);
    if (lane == 0) { g_CNTA[col] = pA; g_CNTB[col] = pB; }
    for (int j = tA + lane; j < pA; j += 32) dstA[j] = (unsigned short)1160;  // zero row
    for (int j = tB + lane; j < pB; j += 32) dstB[j] = (unsigned short)1152;  // zero row
}

// ------- SpMM: 32-wide h rows in smem, conflict-free reads (R13, measured 136us) -
#define SPMM_SMEM (HROWS * 128)
#define COLCHUNK 1280
__global__ void __launch_bounds__(1024, 1) k_spmm() {
    extern __shared__ char smraw[];
    const ulonglong2* sW = (const ulonglong2*)smraw;   // HROWS rows x 128 B
    int tid  = threadIdx.x;
    int hc   = blockIdx.y >> 1;
    int half = blockIdx.y & 1;

    const float4* wsrc = (const float4*)(g_W1Tc + (size_t)(hc * 2 + half) * HROWS * 32);
    float4* sWf = (float4*)smraw;
    for (int i = tid; i < HROWS * 8; i += 1024) sWf[i] = wsrc[i];
    __syncthreads();

    const unsigned short* IDX = half ? g_IDXB : g_IDXA;
    const int*            CNT = half ? g_CNTB : g_CNTA;
    float*                Y   = half ? g_Y1b  : g_Y1a;

    int h4    = tid & 7;
    int cbase = blockIdx.x * COLCHUNK + (tid >> 3);
#pragma unroll 1
    for (int p = 0; p < COLCHUNK / 128; p++) {
        int col = cbase + p * 128;
        if (col >= NCOL) break;
        int ng = CNT[col] >> 3;
        const uint4* il = (const uint4*)(IDX + (size_t)col * IDXC2);
        unsigned long long a0x = 0, a0y = 0, a1x = 0, a1y = 0;
        if (ng) {
            uint4 pk  = __ldg(il);
            uint4 pk1 = __ldg(il + 1);
            for (int g = 0; g < ng; g++) {
                uint4 nx = __ldg(il + g + 2);                  // prefetch depth 2
                int i0 = pk.x & 0xffff, i1 = pk.x >> 16;
                int i2 = pk.y & 0xffff, i3 = pk.y >> 16;
                int i4 = pk.z & 0xffff, i5 = pk.z >> 16;
                int i6 = pk.w & 0xffff, i7 = pk.w >> 16;
                ulonglong2 w0 = sW[i0 * 8 + h4];               // quarter-warp = 1 row
                ulonglong2 w1 = sW[i1 * 8 + h4];
                ulonglong2 w2 = sW[i2 * 8 + h4];
                ulonglong2 w3 = sW[i3 * 8 + h4];
                ulonglong2 w4 = sW[i4 * 8 + h4];
                ulonglong2 w5 = sW[i5 * 8 + h4];
                ulonglong2 w6 = sW[i6 * 8 + h4];
                ulonglong2 w7 = sW[i7 * 8 + h4];
                ADDX2(a0x, a0x, w0.x); ADDX2(a0y, a0y, w0.y);
                ADDX2(a1x, a1x, w1.x); ADDX2(a1y, a1y, w1.y);
                ADDX2(a0x, a0x, w2.x); ADDX2(a0y, a0y, w2.y);
                ADDX2(a1x, a1x, w3.x); ADDX2(a1y, a1y, w3.y);
                ADDX2(a0x, a0x, w4.x); ADDX2(a0y, a0y, w4.y);
                ADDX2(a1x, a1x, w5.x); ADDX2(a1y, a1y, w5.y);
                ADDX2(a0x, a0x, w6.x); ADDX2(a0y, a0y, w6.y);
                ADDX2(a1x, a1x, w7.x); ADDX2(a1y, a1y, w7.y);
                pk = pk1; pk1 = nx;
            }
        }
        float2 p0 = *(float2*)&a0x, q0 = *(float2*)&a0y;
        float2 p1 = *(float2*)&a1x, q1 = *(float2*)&a1y;
        float4 r;
        r.x = p0.x + p1.x; r.y = p0.y + p1.y;
        r.z = q0.x + q1.x; r.w = q0.y + q1.y;
        ((float4*)Y)[(size_t)col * 128 + hc * 8 + h4] = r;
    }
}

// ---- FIR1: template-folded eps immediates (FFMA-imm), fused spike IIR -----------
#define FPAD  112
#define TROWS (FPAD + 384)    // 496
#define FIR_SMEM ((TROWS * 32 + TT * 32) * 4)
__global__ void __launch_bounds__(256, 2) k_fir_spike1() {
    extern __shared__ float sm[];
    float* tile = sm;                     // [TROWS][32], zero-padded front/back
    float* usm  = sm + TROWS * 32;        // [350][32]
    int tid = threadIdx.x;
    int b   = blockIdx.x >> 4;
    int h0  = (blockIdx.x & 15) * 32;

    for (int i = tid; i < FPAD * 32; i += 256) tile[i] = 0.f;
    for (int i = tid; i < (TROWS - FPAD - TT) * 32; i += 256) tile[(FPAD + TT) * 32 + i] = 0.f;
    for (int i = tid; i < TT * 32; i += 256) {
        int t = i >> 5, hl = i & 31;
        size_t off = ((size_t)(b * TT + t)) * NHID + h0 + hl;
        tile[(FPAD + t) * 32 + hl] = g_Y1a[off] + g_Y1b[off];
    }
    __syncthreads();

    int hl = tid & 31, rg = tid >> 5;
#pragma unroll 1
    for (int m = 0; m < 6; m++) {
        int t0 = m * 64 + rg * 8;
        if (t0 >= TT) break;
        float acc[8] = {0, 0, 0, 0, 0, 0, 0, 0};
        const float* base = tile + (FPAD + t0) * 32 + hl;
        JStep<6>::run(base, acc);
#pragma unroll
        for (int r = 0; r < 8; r++) {
            int t = t0 + r;
            if (t < TT) usm[t * 32 + hl] = acc[r];
        }
    }
    __syncthreads();

    if (tid < 32) {                        // per-h refractory IIR over t
        float a = 0.f, rb = 0.f;
        size_t obase = ((size_t)b * TT) * NHID + h0 + tid;
        for (int t = 0; t < TT; t++) {
            float u  = usm[t * 32 + tid] + C_REF * rb;
            float s  = (u >= THETA) ? 1.f : 0.f;
            float an = D_REF * a + s;
            rb = D_REF * rb + D_REF * a;
            a  = an;
            g_S1[obase + (size_t)t * NHID] = s;
        }
    }
}

// ---------------- GEMV2 + FIR2: t-chunked, overlap recompute --------------------
#define TCHUNK 70
#define GEMV_SMEM ((64 * NHID + 169 * NOUT + 128) * 4)
__global__ void __launch_bounds__(512, 1) k_gemv2(const float* __restrict__ W2) {
    extern __shared__ float sm[];
    float* sS1  = sm;                        // [64][512]
    float* sY2  = sm + 64 * NHID;            // [169][10]
    float* seps = sm + 64 * NHID + 169 * NOUT;
    int tid = threadIdx.x;
    int b   = blockIdx.x;
    int tc  = blockIdx.y * TCHUNK;
    int base = tc - 99;
    int rlo = max(0, base), rhi = tc + TCHUNK;

    if (tid < 128) seps[tid] = (tid >= 1 && tid < 100)
                               ? (float)((tid / 10.0) * exp(1.0 - tid / 10.0)) : 0.f;
    for (int i = tid; i < 169 * NOUT; i += 512) sY2[i] = 0.f;

    int wid = tid >> 5, lane = tid & 31;
    for (int r0 = rlo; r0 < rhi; r0 += 64) {
        int rows = min(64, rhi - r0);
        __syncthreads();
        const float4* src = (const float4*)(g_S1 + ((size_t)(b * TT + r0)) * NHID);
        for (int i = tid; i < rows * 128; i += 512) ((float4*)sS1)[i] = src[i];
        __syncthreads();
        for (int task = wid; task < rows * NOUT; task += 16) {
            int tl = task / NOUT, o = task - tl * NOUT;
            float acc = 0.f;
            const float* sp = sS1 + tl * NHID;
            const float* wp = W2 + o * NHID;
#pragma unroll 4
            for (int h = lane; h < NHID; h += 32) acc = fmaf(sp[h], wp[h], acc);
#pragma unroll
            for (int ofs = 16; ofs; ofs >>= 1) acc += __shfl_down_sync(0xffffffffu, acc, ofs);
            if (lane == 0) sY2[(r0 + tl - base) * NOUT + o] = acc;
        }
    }
    __syncthreads();
    for (int i = tid; i < TCHUNK * NOUT; i += 512) {
        int tl = i / NOUT, o = i - tl * NOUT;
        int t = tc + tl;
        float acc = 0.f;
#pragma unroll 4
        for (int k = 1; k < 100; k++)
            acc = fmaf(seps[k], sY2[(t - k - base) * NOUT + o], acc);
        g_U2[(b * TT + t) * NOUT + o] = acc;
    }
}

// ---------------- spike2 IIR (smem-staged, per-batch block) ----------------------
__global__ void __launch_bounds__(256, 4) k_spike2(float* __restrict__ out) {
    __shared__ float su[TT * NOUT];
    __shared__ float ss[NOUT * TT];
    int b = blockIdx.x, tid = threadIdx.x;
    const float4* src = (const float4*)(g_U2 + (size_t)b * TT * NOUT);
    for (int i = tid; i < TT * NOUT / 2; i += 256) {
        float4 v = src[i];
        su[i * 4] = v.x; su[i * 4 + 1] = v.y; su[i * 4 + 2] = v.z; su[i * 4 + 3] = v.w;
    }
    __syncthreads();
    if (tid < NOUT) {
        float a = 0.f, rb = 0.f;
        for (int t = 0; t < TT; t++) {
            float u  = su[t * NOUT + tid] + C_REF * rb;
            float s  = (u >= THETA) ? 1.f : 0.f;
            float an = D_REF * a + s;
            rb = D_REF * rb + D_REF * a;
            a  = an;
            ss[tid * TT + t] = s;
        }
    }
    __syncthreads();
    for (int i = tid; i < NOUT * TT; i += 256)
        out[(size_t)b * NOUT * TT + i] = ss[i];
}

extern "C" void kernel_launch(void* const* d_in, const int* in_sizes, int n_in,
                              void* d_out, int out_size) {
    const float* A  = nullptr;   // spikeInput [B][NIN][T]
    const float* W1 = nullptr;   // [NHID][NIN]
    const float* W2 = nullptr;   // [NOUT][NHID]
    for (int i = 0; i < n_in; i++) {
        if      (in_sizes[i] == BB * NIN * TT) A  = (const float*)d_in[i];
        else if (in_sizes[i] == NHID * NIN)    W1 = (const float*)d_in[i];
        else if (in_sizes[i] == NOUT * NHID)   W2 = (const float*)d_in[i];
    }
    float* out = (float*)d_out;

    cudaFuncSetAttribute(k_spmm,       cudaFuncAttributeMaxDynamicSharedMemorySize, SPMM_SMEM);
    cudaFuncSetAttribute(k_fir_spike1, cudaFuncAttributeMaxDynamicSharedMemorySize, FIR_SMEM);
    cudaFuncSetAttribute(k_gemv2,      cudaFuncAttributeMaxDynamicSharedMemorySize, GEMV_SMEM);

    k_prep  <<<dim3(73, 16), dim3(32, 32)>>>(W1);          // pads zeroed in-line
    k_packex<<<dim3(BB, 11), 1024>>>(A);                   // fused pack+extract
    k_spmm  <<<dim3(9, 32), 1024, SPMM_SMEM>>>();
    k_fir_spike1<<<512, 256, FIR_SMEM>>>();                // launch #4 -> ncu window
    k_gemv2 <<<dim3(BB, TT / TCHUNK), 512, GEMV_SMEM>>>(W2);
    k_spike2<<<BB, 256>>>(out);
}